// round 17
// baseline (speedup 1.0000x reference)
#include <cuda_runtime.h>
#include <cuda_bf16.h>
#include <cuda_fp16.h>
#include <math.h>
#include <stdint.h>

// Problem constants
#define B_   1024
#define N_   24
#define L_   24
#define D_   128
#define V_   40000
#define VOUT 39999           // V-1 output columns
#define VPAD 40064           // 313*128, padded vocab tiles
#define NTILES 313
#define GX 36                // n-tile groups (288 CTAs)
#define ALPHA_ 0.2f
#define NEG_ (-9e15f)

// ---------------- scratch (device globals; no runtime allocation) ----------------
static __device__ float g_Wc[384 * 128];
static __device__ float g_bc[128];
static __device__ float g_posw[24 * 128];
static __device__ float g_h[B_ * N_ * D_];
static __device__ float g_hagg[B_ * N_ * D_];
static __device__ __half g_selh[B_ * D_];       // select fp16
static __device__ __half g_embh[VPAD * D_];     // row v = emb[v+1] in fp16

// ==================== warp-MMA / async-copy helpers (portable PTX, sm_80+) ====================
__device__ __forceinline__ uint32_t smem_u32(const void* p) {
    uint32_t a;
    asm("{ .reg .u64 t; cvta.to.shared.u64 t, %1; cvt.u32.u64 %0, t; }" : "=r"(a) : "l"(p));
    return a;
}
__device__ __forceinline__ void ldsm_x4(uint32_t* r, uint32_t addr) {
    asm volatile("ldmatrix.sync.aligned.m8n8.x4.shared.b16 {%0,%1,%2,%3}, [%4];"
                 : "=r"(r[0]), "=r"(r[1]), "=r"(r[2]), "=r"(r[3]) : "r"(addr));
}
__device__ __forceinline__ void mma_fp16(float* c, const uint32_t* a, const uint32_t* b) {
    asm volatile("mma.sync.aligned.m16n8k16.row.col.f32.f16.f16.f32 "
                 "{%0,%1,%2,%3}, {%4,%5,%6,%7}, {%8,%9}, {%0,%1,%2,%3};"
                 : "+f"(c[0]), "+f"(c[1]), "+f"(c[2]), "+f"(c[3])
                 : "r"(a[0]), "r"(a[1]), "r"(a[2]), "r"(a[3]), "r"(b[0]), "r"(b[1]));
}
__device__ __forceinline__ void cpa16(uint32_t sa, const void* g) {
    asm volatile("{\n\t.reg .u64 gg;\n\tcvta.to.global.u64 gg, %1;\n\t"
                 "cp.async.cg.shared.global [%0], [gg], 16;\n\t}"
                 :: "r"(sa), "l"(g) : "memory");
}
#define CP_COMMIT() asm volatile("cp.async.commit_group;" ::: "memory")
#define CP_WAIT1()  asm volatile("cp.async.wait_group 1;" ::: "memory")

// ====================================================================
// Kernel 0: fold weights + pos projection
// ====================================================================
__global__ void k_precompute(const float* __restrict__ W_img, const float* __restrict__ b_img,
                             const float* __restrict__ W_txt, const float* __restrict__ b_txt,
                             const float* __restrict__ W_fuse, const float* __restrict__ b_fuse,
                             const float* __restrict__ pos_emb, const float* __restrict__ w_1) {
    int row = blockIdx.x;
    int d = threadIdx.x;
    if (row < 128) {
        g_Wc[row * 128 + d] = W_fuse[row * 128 + d];
    } else if (row < 256) {
        int k = row - 128;
        float s = 0.f;
        #pragma unroll 4
        for (int j = 0; j < 128; ++j) s += W_img[k * 128 + j] * W_fuse[(128 + j) * 128 + d];
        g_Wc[row * 128 + d] = s;
    } else if (row < 384) {
        int k = row - 256;
        float s = 0.f;
        #pragma unroll 4
        for (int j = 0; j < 128; ++j) s += W_txt[k * 128 + j] * W_fuse[(256 + j) * 128 + d];
        g_Wc[row * 128 + d] = s;
    } else if (row == 384) {
        float s = b_fuse[d];
        #pragma unroll 4
        for (int j = 0; j < 128; ++j) {
            s += b_img[j] * W_fuse[(128 + j) * 128 + d];
            s += b_txt[j] * W_fuse[(256 + j) * 128 + d];
        }
        g_bc[d] = s;
    } else {
        int l = row - 385;
        const float* pr = pos_emb + (size_t)(23 - l) * 128;
        float s = 0.f;
        #pragma unroll 4
        for (int k = 0; k < 128; ++k) s += pr[k] * w_1[k * 128 + d];
        g_posw[l * 128 + d] = s;
    }
}

// ====================================================================
// Kernel 0b: convert emb[1:] to fp16 (padded to VPAD rows)
// ====================================================================
__global__ __launch_bounds__(256) void k_split_emb(const float* __restrict__ emb) {
    int idx = blockIdx.x * 256 + threadIdx.x;
    int row = idx >> 7;
    int c = idx & 127;
    float x = (row < VOUT) ? emb[(size_t)(row + 1) * 128 + c] : 0.f;
    g_embh[idx] = __float2half(x);
}

// ====================================================================
// Kernel 1: fused multimodal embedding
// ====================================================================
__global__ __launch_bounds__(256) void k_embed(const int* __restrict__ items,
                                               const float* __restrict__ emb,
                                               const float* __restrict__ img_emb,
                                               const float* __restrict__ txt_emb) {
    __shared__ __align__(16) float Ash[32][132];
    __shared__ int ids[32];
    int rowbase = blockIdx.x * 32;
    int tid = threadIdx.x;
    int d = tid & 127;
    int rh = tid >> 7;
    int r0 = rh * 16;

    if (tid < 32) ids[tid] = items[rowbase + tid];

    float acc[16];
    #pragma unroll
    for (int i = 0; i < 16; ++i) acc[i] = 0.f;

    for (int c = 0; c < 3; ++c) {
        __syncthreads();
        const float* src = (c == 0) ? emb : (c == 1) ? img_emb : txt_emb;
        for (int idx = tid; idx < 32 * 128; idx += 256) {
            int r = idx >> 7, cc = idx & 127;
            Ash[r][cc] = src[(size_t)ids[r] * 128 + cc];
        }
        __syncthreads();
        const float* wc = g_Wc + (size_t)c * 128 * 128 + d;
        #pragma unroll 4
        for (int k = 0; k < 128; k += 4) {
            float w0 = wc[(size_t)(k + 0) * 128];
            float w1 = wc[(size_t)(k + 1) * 128];
            float w2 = wc[(size_t)(k + 2) * 128];
            float w3 = wc[(size_t)(k + 3) * 128];
            #pragma unroll
            for (int rr = 0; rr < 16; ++rr) {
                float4 s4 = *(const float4*)&Ash[r0 + rr][k];
                acc[rr] += s4.x * w0 + s4.y * w1 + s4.z * w2 + s4.w * w3;
            }
        }
    }
    float bias = g_bc[d];
    #pragma unroll
    for (int rr = 0; rr < 16; ++rr)
        g_h[(size_t)(rowbase + r0 + rr) * 128 + d] = acc[rr] + bias;
}

// ====================================================================
// Kernel 2: RGAT layer — 8-lanes-per-pair (4 pairs/warp, 3 shfl steps).
// ====================================================================
__global__ __launch_bounds__(256) void k_rgat(const int* __restrict__ adj,
                                              const float* __restrict__ a_rel) {
    __shared__ __align__(16) float hsh[24][132];
    __shared__ float esh[24][24];
    __shared__ __align__(16) float arel[4][132];
    __shared__ int adjs[576];
    int b = blockIdx.x;
    int tid = threadIdx.x;
    int wid = tid >> 5, lane = tid & 31;

    for (int idx = tid; idx < 24 * 128; idx += 256)
        hsh[idx >> 7][idx & 127] = g_h[(size_t)b * (24 * 128) + idx];
    for (int idx = tid; idx < 4 * 128; idx += 256)
        arel[idx >> 7][idx & 127] = a_rel[idx];
    for (int idx = tid; idx < 576; idx += 256)
        adjs[idx] = adj[b * 576 + idx];
    __syncthreads();

    int s_ = lane & 7, g_ = lane >> 3;
    for (int q = wid * 4 + g_; q < 576; q += 32) {
        int i = q / 24, j = q - i * 24;
        int a = adjs[q];
        const float* ar = arel[(a > 0) ? (a - 1) : 0];
        float sum = 0.f;
        #pragma unroll
        for (int c = 0; c < 4; ++c) {
            int d0 = s_ * 4 + c * 32;
            float4 hi = *(const float4*)&hsh[i][d0];
            float4 hj = *(const float4*)&hsh[j][d0];
            float4 aa = *(const float4*)&ar[d0];
            sum += hi.x * hj.x * aa.x + hi.y * hj.y * aa.y
                 + hi.z * hj.z * aa.z + hi.w * hj.w * aa.w;
        }
        sum += __shfl_xor_sync(0xffffffffu, sum, 1);
        sum += __shfl_xor_sync(0xffffffffu, sum, 2);
        sum += __shfl_xor_sync(0xffffffffu, sum, 4);
        float v = (a == 0) ? NEG_ : ((sum > 0.f) ? sum : ALPHA_ * sum);
        if (s_ == 0) esh[i][j] = v;
    }
    __syncthreads();

    if (tid < 24) {
        float mx = -INFINITY;
        #pragma unroll
        for (int j = 0; j < 24; ++j) mx = fmaxf(mx, esh[tid][j]);
        float sum = 0.f;
        #pragma unroll
        for (int j = 0; j < 24; ++j) {
            float e = expf(esh[tid][j] - mx);
            esh[tid][j] = e;
            sum += e;
        }
        float inv = 1.f / sum;
        #pragma unroll
        for (int j = 0; j < 24; ++j) esh[tid][j] *= inv;
    }
    __syncthreads();

    for (int idx = tid; idx < 24 * 128; idx += 256) {
        int i = idx >> 7, d2 = idx & 127;
        float s = 0.f;
        #pragma unroll
        for (int j = 0; j < 24; ++j) s += esh[i][j] * hsh[j][d2];
        g_hagg[(size_t)b * (24 * 128) + idx] = s;
    }
}

// ====================================================================
// Kernel 3: session readout (k-outer), writes fp16 select
// ====================================================================
__global__ __launch_bounds__(128) void k_readout(const int* __restrict__ alias_,
                                                 const int* __restrict__ mask_,
                                                 const float* __restrict__ w_1,
                                                 const float* __restrict__ w_2,
                                                 const float* __restrict__ glu1_w,
                                                 const float* __restrict__ glu1_b,
                                                 const float* __restrict__ glu2_w) {
    __shared__ __align__(16) float seq[24][128];
    __shared__ __align__(16) float nhsh[24][128];
    __shared__ float hssh[128];
    __shared__ int al[24];
    __shared__ float mk[24];
    __shared__ float betash[24];
    int b = blockIdx.x;
    int d = threadIdx.x;

    if (d < 24) {
        al[d] = alias_[b * 24 + d];
        mk[d] = (float)mask_[b * 24 + d];
    }
    __syncthreads();
    #pragma unroll
    for (int l = 0; l < 24; ++l)
        seq[l][d] = g_hagg[((size_t)b * 24 + al[l]) * 128 + d];
    __syncthreads();

    float msum = 0.f, hs = 0.f;
    #pragma unroll
    for (int l = 0; l < 24; ++l) { msum += mk[l]; hs += mk[l] * seq[l][d]; }
    hs /= fmaxf(msum, 1.f);
    hssh[d] = hs;
    __syncthreads();

    float hsg = 0.f;
    #pragma unroll 4
    for (int k = 0; k < 128; ++k) hsg += hssh[k] * glu2_w[k * 128 + d];

    float acc[24];
    #pragma unroll
    for (int l = 0; l < 24; ++l) acc[l] = g_posw[l * 128 + d];

    #pragma unroll 2
    for (int k = 0; k < 128; k += 4) {
        float w0 = w_1[(128 + k + 0) * 128 + d];
        float w1 = w_1[(128 + k + 1) * 128 + d];
        float w2c = w_1[(128 + k + 2) * 128 + d];
        float w3 = w_1[(128 + k + 3) * 128 + d];
        #pragma unroll
        for (int l = 0; l < 24; ++l) {
            float4 s4 = *(const float4*)&seq[l][k];
            acc[l] += s4.x * w0 + s4.y * w1 + s4.z * w2c + s4.w * w3;
        }
    }
    #pragma unroll
    for (int l = 0; l < 24; ++l) nhsh[l][d] = tanhf(acc[l]);
    __syncthreads();

    float base = glu1_b[d] + hsg;
    #pragma unroll
    for (int l = 0; l < 24; ++l) acc[l] = base;

    #pragma unroll 2
    for (int k = 0; k < 128; k += 4) {
        float w0 = glu1_w[(k + 0) * 128 + d];
        float w1 = glu1_w[(k + 1) * 128 + d];
        float w2c = glu1_w[(k + 2) * 128 + d];
        float w3 = glu1_w[(k + 3) * 128 + d];
        #pragma unroll
        for (int l = 0; l < 24; ++l) {
            float4 s4 = *(const float4*)&nhsh[l][k];
            acc[l] += s4.x * w0 + s4.y * w1 + s4.z * w2c + s4.w * w3;
        }
    }
    float w2d = w_2[d];
    __syncthreads();
    #pragma unroll
    for (int l = 0; l < 24; ++l)
        nhsh[l][d] = (1.f / (1.f + expf(-acc[l]))) * w2d;
    __syncthreads();

    if (d < 24) {
        float s = 0.f;
        #pragma unroll 8
        for (int k = 0; k < 128; k += 4) {
            float4 p4 = *(const float4*)&nhsh[d][k];
            s += p4.x + p4.y + p4.z + p4.w;
        }
        betash[d] = s * mk[d];
    }
    __syncthreads();

    float sel = 0.f;
    #pragma unroll
    for (int l = 0; l < 24; ++l) sel += betash[l] * seq[l][d];

    g_selh[b * 128 + d] = __float2half(sel);
}

// ====================================================================
// Kernel 4: scores — pipelined single-term fp16 MMA: A * B.
// Grid (GX=36, 8) = 288 CTAs. CTA owns 128 A rows resident in smem;
// loops n-tiles with cp.async double-buffered B tiles.
// 512 threads = 16 warps (8m x 2n), warp tile 16m x 64n.
// smem: A (34KB) + B 2 stages (2x34KB) = 104448 B -> up to 2 CTAs/SM.
// ====================================================================
#define PADK 136
#define TILE_ELEMS (128 * PADK)

__device__ __forceinline__ void prefetch_B(__half* bh, int t, int tid) {
    const __half* sh = g_embh + (size_t)t * (128 * 128);
    uint32_t bha = smem_u32(bh);
    for (int i = tid; i < 2048; i += 512) {
        int r = i >> 4, c = i & 15;
        cpa16(bha + (uint32_t)(r * PADK + c * 8) * 2, sh + r * 128 + c * 8);
    }
}

__global__ __launch_bounds__(512) void k_scores_mma(float* __restrict__ out) {
    extern __shared__ __align__(16) __half smem[];
    __half* Ahs = smem;                       // [128][136]
    __half* Bbuf = Ahs + TILE_ELEMS;          // 2 stages

    int tid = threadIdx.x;
    int bx = blockIdx.x;
    int m0 = blockIdx.y * 128;

    // prologue: A (resident) + B tile 0 -> group 0; B tile 1 -> group 1
    {
        uint32_t aha = smem_u32(Ahs);
        const __half* sh = g_selh + (size_t)m0 * 128;
        for (int i = tid; i < 2048; i += 512) {
            int r = i >> 4, c = i & 15;
            cpa16(aha + (uint32_t)(r * PADK + c * 8) * 2, sh + r * 128 + c * 8);
        }
        prefetch_B(Bbuf, bx, tid);
        CP_COMMIT();
        if (bx + GX < NTILES)
            prefetch_B(Bbuf + TILE_ELEMS, bx + GX, tid);
        CP_COMMIT();
    }

    int wid = tid >> 5, lid = tid & 31;
    int wm = (wid & 7) * 16;       // warp m offset
    int wn = (wid >> 3) * 64;      // warp n offset
    uint32_t aH = smem_u32(Ahs);

    int a_row = ((lid >> 3) & 1) * 8 + (lid & 7);
    int a_kof = ((lid >> 4) & 1) * 8;
    int b_n = ((lid >> 4) & 1) * 8 + (lid & 7);
    int b_kof = ((lid >> 3) & 1) * 8;

    int cur = 0;
    for (int t = bx; t < NTILES; t += GX, cur ^= 1) {
        CP_WAIT1();
        __syncthreads();

        uint32_t bH = smem_u32(Bbuf + cur * TILE_ELEMS);

        float c[8][4];
        #pragma unroll
        for (int ni = 0; ni < 8; ++ni)
            #pragma unroll
            for (int j = 0; j < 4; ++j) c[ni][j] = 0.f;

        #pragma unroll
        for (int kb = 0; kb < 128; kb += 16) {
            uint32_t ah[4], bh[8][2];
            uint32_t aoff = (uint32_t)((wm + a_row) * PADK + kb + a_kof) * 2;
            ldsm_x4(ah, aH + aoff);
            #pragma unroll
            for (int jj = 0; jj < 4; ++jj) {
                uint32_t off = (uint32_t)((wn + jj * 16 + b_n) * PADK + kb + b_kof) * 2;
                uint32_t r[4];
                ldsm_x4(r, bH + off);
                bh[2 * jj][0] = r[0]; bh[2 * jj][1] = r[1];
                bh[2 * jj + 1][0] = r[2]; bh[2 * jj + 1][1] = r[3];
            }
            #pragma unroll
            for (int ni = 0; ni < 8; ++ni)
                mma_fp16(c[ni], ah, bh[ni]);
        }

        // store this tile
        int r0 = m0 + wm + (lid >> 2);
        int c0 = t * 128 + wn + (lid & 3) * 2;
        float* p0 = out + (size_t)r0 * VOUT;
        float* p1 = out + (size_t)(r0 + 8) * VOUT;
        #pragma unroll
        for (int ni = 0; ni < 8; ++ni) {
            int gc = c0 + ni * 8;
            if (gc < VOUT)     p0[gc]     = c[ni][0];
            if (gc + 1 < VOUT) p0[gc + 1] = c[ni][1];
            if (gc < VOUT)     p1[gc]     = c[ni][2];
            if (gc + 1 < VOUT) p1[gc + 1] = c[ni][3];
        }

        __syncthreads();   // all warps done reading buf[cur] before refill
        int tn = t + 2 * GX;
        if (tn < NTILES)
            prefetch_B(Bbuf + cur * TILE_ELEMS, tn, tid);
        CP_COMMIT();       // commit every iteration (possibly empty group)
    }
}

// ====================================================================
// launch
// ====================================================================
extern "C" void kernel_launch(void* const* d_in, const int* in_sizes, int n_in,
                              void* d_out, int out_size) {
    const int*   items   = (const int*)d_in[0];
    const int*   adj     = (const int*)d_in[1];
    const int*   alias_  = (const int*)d_in[2];
    const int*   mask_   = (const int*)d_in[3];
    const float* emb     = (const float*)d_in[4];
    const float* img_emb = (const float*)d_in[5];
    const float* txt_emb = (const float*)d_in[6];
    const float* W_img   = (const float*)d_in[7];
    const float* b_img   = (const float*)d_in[8];
    const float* W_txt   = (const float*)d_in[9];
    const float* b_txt   = (const float*)d_in[10];
    const float* W_fuse  = (const float*)d_in[11];
    const float* b_fuse  = (const float*)d_in[12];
    const float* a_rel   = (const float*)d_in[13];
    const float* pos_emb = (const float*)d_in[14];
    const float* w_1     = (const float*)d_in[15];
    const float* w_2     = (const float*)d_in[16];
    const float* glu1_w  = (const float*)d_in[17];
    const float* glu1_b  = (const float*)d_in[18];
    const float* glu2_w  = (const float*)d_in[19];
    float* out = (float*)d_out;

    k_precompute<<<409, 128>>>(W_img, b_img, W_txt, b_txt, W_fuse, b_fuse, pos_emb, w_1);
    k_split_emb<<<(VPAD * 128) / 256, 256>>>(emb);
    k_embed<<<(B_ * N_) / 32, 256>>>(items, emb, img_emb, txt_emb);
    k_rgat<<<B_, 256>>>(adj, a_rel);
    k_readout<<<B_, 128>>>(alias_, mask_, w_1, w_2, glu1_w, glu1_b, glu2_w);

    int smem_bytes = 3 * TILE_ELEMS * (int)sizeof(__half);  // 104448
    cudaFuncSetAttribute(k_scores_mma, cudaFuncAttributeMaxDynamicSharedMemorySize, smem_bytes);
    dim3 grid(GX, B_ / 128);   // 36 x 8 = 288 CTAs
    k_scores_mma<<<grid, 512, smem_bytes>>>(out);
}